// round 9
// baseline (speedup 1.0000x reference)
#include <cuda_runtime.h>
#include <cuda_bf16.h>
#include <math.h>

// Problem constants
#define B_DIM 16
#define S_DIM 4096
#define F_DIM 512
#define NCLS 10
#define HID 64
#define ODIM 128

#define COLS_PER_CTA 4
#define NTHREADS 1024
#define ROWS_PER_THREAD (S_DIM / (NTHREADS / COLS_PER_CTA))   // 16
#define TAB_SLOTS 8192          // per-column hash slots (<=4096 distinct -> LF 0.5)
#define EMPTY_SLOT 0xFFFFFFFFu  // canonicalized values never have this bit pattern

// Shared memory (dynamic), bytes:
// phase 1: [0, 131072)       4 hash tables of 8192 u32
//          [131072, 135168)  y labels for this batch as u8 (4096)
// phase 2 overlay (inside tables region, after __syncthreads):
//          [0, 4096)         red: 32 warps x 32 floats (4 cols? no: [warp][col*14+stat])
//          [4096, 4352)      tot: 4 cols x 16 stats
//          [4352, 4448)      stats6: 4 cols x 6
//          [4608, 5632)      h: 4 cols x 64
//          [8192, 40960)     w2 staged (64x128 f32)
#define OFF_TABLES   0
#define OFF_Y8       131072
#define OFF_RED      0
#define OFF_TOT      4096
#define OFF_STATS    4352
#define OFF_H        4608
#define OFF_W2       8192
#define SMEM_BYTES   135168

__device__ float g_class_counts[B_DIM * NCLS];

__global__ void class_count_kernel(const int* __restrict__ y) {
    __shared__ int hist[NCLS];
    int b = blockIdx.x;
    if (threadIdx.x < NCLS) hist[threadIdx.x] = 0;
    __syncthreads();
    for (int i = threadIdx.x; i < S_DIM; i += blockDim.x)
        atomicAdd(&hist[y[b * S_DIM + i]], 1);
    __syncthreads();
    if (threadIdx.x < NCLS) g_class_counts[b * NCLS + threadIdx.x] = (float)hist[threadIdx.x];
}

// Exact distinct-count insert: Fibonacci hash, CAS-first, linear probe on rare
// collisions. Unique total = number of CAS winners -> race-order invariant.
__device__ __forceinline__ void hins(unsigned int* __restrict__ tab, float v, float& uniq) {
    unsigned int bits = __float_as_uint(v);
    bits = (v == 0.0f) ? 0u : bits;                 // -0 -> +0 canonicalization
    unsigned int slot = (bits * 2654435761u) >> 19; // top 13 bits
    unsigned int cur = atomicCAS(tab + slot, EMPTY_SLOT, bits);
    while (cur != EMPTY_SLOT && cur != bits) {
        slot = (slot + 1) & (TAB_SLOTS - 1);
        cur = atomicCAS(tab + slot, EMPTY_SLOT, bits);
    }
    if (cur == EMPTY_SLOT) uniq += 1.0f;
}

__global__ __launch_bounds__(NTHREADS, 1)
void stats_mlp_kernel(const float* __restrict__ X,
                      const int*   __restrict__ y,
                      const float* __restrict__ w1,
                      const float* __restrict__ b1,
                      const float* __restrict__ w2,
                      const float* __restrict__ b2,
                      float* __restrict__ out) {
    extern __shared__ char smem[];
    unsigned int* tables = (unsigned int*)(smem + OFF_TABLES);
    unsigned char* y8 = (unsigned char*)(smem + OFF_Y8);

    const int tid  = threadIdx.x;
    const int lane = tid & 31;
    const int wid  = tid >> 5;
    const int g  = blockIdx.x;       // feature group 0..127
    const int b  = blockIdx.y;       // batch 0..15
    const int f0 = g * COLS_PER_CTA;

    // init hash tables (32768 words) with EMPTY (vectorized)
    {
        uint4* tv = (uint4*)tables;
        uint4 e = make_uint4(EMPTY_SLOT, EMPTY_SLOT, EMPTY_SLOT, EMPTY_SLOT);
        #pragma unroll
        for (int i = 0; i < (COLS_PER_CTA * TAB_SLOTS / 4) / NTHREADS; i++)
            tv[tid + i * NTHREADS] = e;
    }
    // stage y as bytes
    #pragma unroll
    for (int i = 0; i < S_DIM / NTHREADS; i++)
        y8[tid + i * NTHREADS] = (unsigned char)y[b * S_DIM + tid + i * NTHREADS];
    __syncthreads();

    const int col = tid & 3;         // 4 consecutive lanes read 16 contiguous bytes
    const int r0  = tid >> 2;        // 0..255

    float sum = 0.f, sumsq = 0.f, sumabs = 0.f, maxabs = 0.f, nanc = 0.f;
    float uniq = 0.f;
    float csum[NCLS - 1];            // class 9 derived as sum - others
    #pragma unroll
    for (int c = 0; c < NCLS - 1; c++) csum[c] = 0.f;

    unsigned int* tab = tables + col * TAB_SLOTS;
    const float* Xb = X + ((size_t)b * S_DIM) * F_DIM + f0 + col;

    #pragma unroll 8
    for (int i = 0; i < ROWS_PER_THREAD; i++) {
        const int r = r0 + 256 * i;
        float x = __ldg(&Xb[(size_t)r * F_DIM]);
        int yv = (int)y8[r];
        bool isn = isnan(x);
        float v = isn ? 0.0f : x;
        nanc += isn ? 1.0f : 0.0f;
        sum += v;
        sumsq = fmaf(v, v, sumsq);
        float a = fabsf(v);
        sumabs += a;
        maxabs = fmaxf(maxabs, a);
        #pragma unroll
        for (int c = 0; c < NCLS - 1; c++)
            csum[c] += (yv == c) ? v : 0.0f;

        hins(tab, v, uniq);
    }
    __syncthreads();   // tables & y8 done; tables region reusable as overlay

    float* red    = (float*)(smem + OFF_RED);    // [32 warps][32]: col-pair packing
    float* tot    = (float*)(smem + OFF_TOT);    // [4][16]
    float* stats6 = (float*)(smem + OFF_STATS);
    float* hsm    = (float*)(smem + OFF_H);
    float* w2s    = (float*)(smem + OFF_W2);

    // ---- warp butterfly reduce 15 stats down to per-col (stop at offset 4) ----
    {
        float st[15];
        st[0] = sum; st[1] = sumsq; st[2] = sumabs; st[3] = maxabs;
        st[4] = nanc; st[5] = uniq;
        #pragma unroll
        for (int c = 0; c < NCLS - 1; c++) st[6 + c] = csum[c];
        #pragma unroll
        for (int k = 0; k < 15; k++) {
            float v = st[k];
            #pragma unroll
            for (int off = 16; off >= 4; off >>= 1) {
                float o = __shfl_xor_sync(0xFFFFFFFFu, v, off);
                v = (k == 3) ? fmaxf(v, o) : v + o;
            }
            st[k] = v;
        }
        // lanes 0..3 hold per-col partials; pack two cols per 32-float row
        if (lane < 4) {
            #pragma unroll
            for (int k = 0; k < 15; k++)
                red[(wid * 2 + (lane >> 1)) * 32 + (lane & 1) * 15 + k] = st[k];
        }
    }
    __syncthreads();

    // ---- cross-warp totals: threads 0..59 each own one (col, stat) ----
    if (tid < 60) {
        int c = tid / 15, s = tid % 15;   // c: col 0..3, s: stat 0..14
        int row0 = c >> 1, half = c & 1;
        float v = red[(0 * 2 + row0) * 32 + half * 15 + s];
        #pragma unroll
        for (int w = 1; w < 32; w++) {
            float o = red[(w * 2 + row0) * 32 + half * 15 + s];
            v = (s == 3) ? fmaxf(v, o) : v + o;
        }
        tot[c * 16 + s] = v;
    }
    // stage w2 into smem (all threads; disjoint region)
    {
        const float4* w2v = (const float4*)w2;
        float4* w2d = (float4*)w2s;
        #pragma unroll
        for (int i = 0; i < (HID * ODIM / 4) / NTHREADS; i++)
            w2d[tid + i * NTHREADS] = w2v[tid + i * NTHREADS];
    }
    __syncthreads();

    // ---- per-column final stats (threads 0..3) ----
    if (tid < COLS_PER_CTA) {
        const float Sf = (float)S_DIM;
        float tsum    = tot[tid * 16 + 0];
        float tsumsq  = tot[tid * 16 + 1];
        float tsumabs = tot[tid * 16 + 2];
        float tmaxabs = tot[tid * 16 + 3];
        float tnan    = tot[tid * 16 + 4];
        float tuniq   = tot[tid * 16 + 5];
        float gmean = tsum / Sf;
        float var = fmaxf(tsumsq / Sf - gmean * gmean, 0.0f);
        float cs9 = tsum;
        #pragma unroll
        for (int c = 0; c < NCLS - 1; c++) cs9 -= tot[tid * 16 + 6 + c];
        float between = 0.0f;
        #pragma unroll
        for (int c = 0; c < NCLS; c++) {
            float cnt = g_class_counts[b * NCLS + c];
            float cs = (c < NCLS - 1) ? tot[tid * 16 + 6 + c] : cs9;
            float cm = cs / fmaxf(cnt, 1.0f);
            float d = cm - gmean;
            between = fmaf(cnt, d * d, between);
        }
        between /= Sf;
        stats6[tid * 6 + 0] = between / fmaxf(var, 1e-6f);
        stats6[tid * 6 + 1] = tnan / Sf;
        stats6[tid * 6 + 2] = tuniq / Sf;
        stats6[tid * 6 + 3] = var;
        stats6[tid * 6 + 4] = tsumabs / Sf;
        stats6[tid * 6 + 5] = tmaxabs;
    }
    __syncthreads();

    // ---- MLP layer 1: h = gelu_exact(stats6 @ w1 + b1), 4 cols x 64 ----
    if (tid < COLS_PER_CTA * HID) {
        int ch = tid >> 6, j = tid & 63;
        float acc = b1[j];
        #pragma unroll
        for (int i = 0; i < 6; i++)
            acc = fmaf(stats6[ch * 6 + i], w1[i * HID + j], acc);
        hsm[ch * HID + j] = 0.5f * acc * (1.0f + erff(acc * 0.70710678118654752f));
    }
    __syncthreads();

    // ---- MLP layer 2: out = h @ w2 + b2, 4 cols x 128 (one output/thread) ----
    if (tid < COLS_PER_CTA * ODIM) {
        int ch = tid >> 7, k = tid & 127;
        float acc = b2[k];
        #pragma unroll
        for (int j = 0; j < HID; j++)
            acc = fmaf(hsm[ch * HID + j], w2s[j * ODIM + k], acc);
        out[(((size_t)b * F_DIM) + f0 + ch) * ODIM + k] = acc;
    }
}

extern "C" void kernel_launch(void* const* d_in, const int* in_sizes, int n_in,
                              void* d_out, int out_size) {
    const float* X  = (const float*)d_in[0];
    const int*   y  = (const int*)d_in[1];
    const float* w1 = (const float*)d_in[2];
    const float* b1 = (const float*)d_in[3];
    const float* w2 = (const float*)d_in[4];
    const float* b2 = (const float*)d_in[5];
    float* out = (float*)d_out;

    cudaFuncSetAttribute(stats_mlp_kernel,
                         cudaFuncAttributeMaxDynamicSharedMemorySize, SMEM_BYTES);

    class_count_kernel<<<B_DIM, 256>>>(y);
    dim3 grid(F_DIM / COLS_PER_CTA, B_DIM);
    stats_mlp_kernel<<<grid, NTHREADS, SMEM_BYTES>>>(X, y, w1, b1, w2, b2, out);
}

// round 10
// speedup vs baseline: 2.0540x; 2.0540x over previous
#include <cuda_runtime.h>
#include <cuda_bf16.h>
#include <math.h>

// Problem constants
#define B_DIM 16
#define S_DIM 4096
#define F_DIM 512
#define NCLS 10
#define HID 64
#define ODIM 128

#define COLS_PER_CTA 4
#define NTHREADS 1024
#define ROWS_PER_THREAD 16
#define TAB_SLOTS 8192          // per-column hash slots (<=4096 distinct -> LF 0.5)
#define EMPTY_SLOT 0xFFFFFFFFu  // canonicalized values never have this bit pattern

// Shared memory (dynamic), bytes:
// phase 1: [0, 131072)        4 hash tables of 8192 u32
//          [131072, 139264)   perm (4096 u16, class-sorted row ids)
//          [139264, 139328)   class_start (11 ints, padded)
//          [139328, 139520)   bins (4 cols x 10 classes f32, padded)
// phase 2 overlay (inside tables region, after __syncthreads):
//          [0, 4096)          red: 32 warps x 32 floats
//          [4096, 4352)       tot: 4 cols x 8 stats
//          [4352, 4448)       stats6: 4 cols x 6
//          [4608, 5632)       h: 4 cols x 64
//          [8192, 40960)      w2 staged (64x128 f32)
#define OFF_TABLES   0
#define OFF_PERM     131072
#define OFF_CS       139264
#define OFF_BINS     139328
#define SMEM_BYTES   139520
#define OFF_RED      0
#define OFF_TOT      4096
#define OFF_STATS    4352
#define OFF_H        4608
#define OFF_W2       8192

__device__ float g_class_counts[B_DIM * NCLS];
__device__ int g_cs[B_DIM * 12];                    // class_start prefix per batch
__device__ unsigned short g_perm[B_DIM * S_DIM];    // class-sorted row ids

// ---- per-batch stable counting sort of row indices by class ----
__global__ void sort_kernel(const int* __restrict__ y) {
    __shared__ int scnt[256 * 10];
    __shared__ int spos[256 * 10];
    __shared__ int cs[12];
    const int t = threadIdx.x;
    const int b = blockIdx.x;
    const int* yb = y + b * S_DIM;

    #pragma unroll
    for (int c = 0; c < NCLS; c++) scnt[t * 10 + c] = 0;
    __syncthreads();
    // pass 1: per-thread class counts over its contiguous 16 rows
    #pragma unroll
    for (int i = 0; i < 16; i++) scnt[t * 10 + yb[t * 16 + i]]++;
    __syncthreads();
    // column-wise exclusive prefix over threads (10 threads, serial over 256)
    if (t < NCLS) {
        int run = 0;
        for (int tt = 0; tt < 256; tt++) {
            spos[tt * 10 + t] = run;
            run += scnt[tt * 10 + t];
        }
        g_class_counts[b * NCLS + t] = (float)run;
        scnt[t] = run;  // reuse row 0 area for totals (safe: pass1 data consumed)
    }
    __syncthreads();
    if (t == 0) {
        int acc = 0;
        #pragma unroll
        for (int c = 0; c < NCLS; c++) { cs[c] = acc; acc += scnt[c]; }
        cs[10] = acc;   // == 4096
        #pragma unroll
        for (int c = 0; c < 11; c++) g_cs[b * 12 + c] = cs[c];
    }
    __syncthreads();
    // pass 2: stable scatter
    #pragma unroll
    for (int i = 0; i < 16; i++) {
        int c = yb[t * 16 + i];
        int idx = cs[c] + spos[t * 10 + c];
        spos[t * 10 + c] = spos[t * 10 + c] + 1;
        g_perm[b * S_DIM + idx] = (unsigned short)(t * 16 + i);
    }
}

// Exact distinct-count insert: Fibonacci hash, CAS-first, linear probe on rare
// collisions. Unique total = number of CAS winners -> race-order invariant.
__device__ __forceinline__ void hins(unsigned int* __restrict__ tab, float v, float& uniq) {
    unsigned int bits = __float_as_uint(v);
    bits = (v == 0.0f) ? 0u : bits;                 // -0 -> +0 canonicalization
    unsigned int slot = (bits * 2654435761u) >> 19; // top 13 bits
    unsigned int cur = atomicCAS(tab + slot, EMPTY_SLOT, bits);
    while (cur != EMPTY_SLOT && cur != bits) {
        slot = (slot + 1) & (TAB_SLOTS - 1);
        cur = atomicCAS(tab + slot, EMPTY_SLOT, bits);
    }
    if (cur == EMPTY_SLOT) uniq += 1.0f;
}

__global__ __launch_bounds__(NTHREADS, 1)
void stats_mlp_kernel(const float* __restrict__ X,
                      const float* __restrict__ w1,
                      const float* __restrict__ b1,
                      const float* __restrict__ w2,
                      const float* __restrict__ b2,
                      float* __restrict__ out) {
    extern __shared__ char smem[];
    unsigned int* tables = (unsigned int*)(smem + OFF_TABLES);
    unsigned short* perm = (unsigned short*)(smem + OFF_PERM);
    int* cs = (int*)(smem + OFF_CS);
    float* bins = (float*)(smem + OFF_BINS);   // [col][class]

    const int tid  = threadIdx.x;
    const int lane = tid & 31;
    const int wid  = tid >> 5;
    const int g  = blockIdx.x;       // feature group 0..127
    const int b  = blockIdx.y;       // batch 0..15
    const int f0 = g * COLS_PER_CTA;

    // init hash tables (vectorized)
    {
        uint4* tv = (uint4*)tables;
        uint4 e = make_uint4(EMPTY_SLOT, EMPTY_SLOT, EMPTY_SLOT, EMPTY_SLOT);
        #pragma unroll
        for (int i = 0; i < (COLS_PER_CTA * TAB_SLOTS / 4) / NTHREADS; i++)
            tv[tid + i * NTHREADS] = e;
    }
    // stage perm (8192B) via uint2
    {
        const uint2* ps = (const uint2*)(g_perm + b * S_DIM);
        uint2* pd = (uint2*)perm;
        pd[tid] = ps[tid];
    }
    if (tid < 11) cs[tid] = g_cs[b * 12 + tid];
    if (tid < COLS_PER_CTA * NCLS) bins[tid] = 0.0f;
    __syncthreads();

    const int col  = tid & 3;        // 4 consecutive lanes read 16 contiguous bytes
    const int r0   = tid >> 2;       // 0..255
    const int base = r0 * ROWS_PER_THREAD;

    float sumsq = 0.f, sumabs = 0.f, maxabs = 0.f, nanc = 0.f, uniq = 0.f;
    float acc = 0.f;                 // running class-segment sum

    // starting class for this thread's contiguous row range
    int cur = 0;
    #pragma unroll
    for (int c = 0; c < NCLS - 1; c++) cur += (cs[c + 1] <= base) ? 1 : 0;
    int nxt = cs[cur + 1];

    unsigned int* tab = tables + col * TAB_SLOTS;
    const float* Xb = X + ((size_t)b * S_DIM) * F_DIM + f0 + col;
    float* mybin = bins + col * NCLS;

    #pragma unroll 4
    for (int i = 0; i < ROWS_PER_THREAD; i++) {
        const int p = base + i;
        if (p == nxt) {              // class boundary (rare)
            atomicAdd(mybin + cur, acc);
            acc = 0.f;
            do { cur++; nxt = cs[cur + 1]; } while (nxt == p);
        }
        int row = (int)perm[p];
        float x = __ldg(&Xb[(size_t)row * F_DIM]);
        bool isn = isnan(x);
        float v = isn ? 0.0f : x;
        nanc += isn ? 1.0f : 0.0f;
        acc += v;
        sumsq = fmaf(v, v, sumsq);
        float a = fabsf(v);
        sumabs += a;
        maxabs = fmaxf(maxabs, a);
        hins(tab, v, uniq);
    }
    atomicAdd(mybin + cur, acc);     // final segment flush
    __syncthreads();                 // bins & tables final; tables -> overlay

    float* red    = (float*)(smem + OFF_RED);    // [32 warps][32]
    float* tot    = (float*)(smem + OFF_TOT);    // [4][8]
    float* stats6 = (float*)(smem + OFF_STATS);
    float* hsm    = (float*)(smem + OFF_H);
    float* w2s    = (float*)(smem + OFF_W2);

    // ---- warp butterfly reduce 5 stats to per-col (stop at offset 4) ----
    {
        float st[5] = {sumsq, sumabs, maxabs, nanc, uniq};
        #pragma unroll
        for (int k = 0; k < 5; k++) {
            float v = st[k];
            #pragma unroll
            for (int off = 16; off >= 4; off >>= 1) {
                float o = __shfl_xor_sync(0xFFFFFFFFu, v, off);
                v = (k == 2) ? fmaxf(v, o) : v + o;
            }
            st[k] = v;
        }
        if (lane < 4) {
            #pragma unroll
            for (int k = 0; k < 5; k++) red[wid * 32 + lane * 8 + k] = st[k];
        }
    }
    __syncthreads();

    // ---- cross-warp totals: threads 0..31, c=tid>>3, k=tid&7 (k<5 used) ----
    if (tid < 32 && (tid & 7) < 5) {
        int c = tid >> 3, k = tid & 7;
        float v = red[0 * 32 + c * 8 + k];
        #pragma unroll
        for (int w = 1; w < 32; w++) {
            float o = red[w * 32 + c * 8 + k];
            v = (k == 2) ? fmaxf(v, o) : v + o;
        }
        tot[c * 8 + k] = v;
    }
    // stage w2 (disjoint region)
    {
        const float4* w2v = (const float4*)w2;
        float4* w2d = (float4*)w2s;
        #pragma unroll
        for (int i = 0; i < (HID * ODIM / 4) / NTHREADS; i++)
            w2d[tid + i * NTHREADS] = w2v[tid + i * NTHREADS];
    }
    __syncthreads();

    // ---- per-column final stats (threads 0..3) ----
    if (tid < COLS_PER_CTA) {
        const float Sf = (float)S_DIM;
        float tsumsq  = tot[tid * 8 + 0];
        float tsumabs = tot[tid * 8 + 1];
        float tmaxabs = tot[tid * 8 + 2];
        float tnan    = tot[tid * 8 + 3];
        float tuniq   = tot[tid * 8 + 4];
        float tsum = 0.f;
        #pragma unroll
        for (int c = 0; c < NCLS; c++) tsum += bins[tid * NCLS + c];
        float gmean = tsum / Sf;
        float var = fmaxf(tsumsq / Sf - gmean * gmean, 0.0f);
        float between = 0.0f;
        #pragma unroll
        for (int c = 0; c < NCLS; c++) {
            float cnt = g_class_counts[b * NCLS + c];
            float cm = bins[tid * NCLS + c] / fmaxf(cnt, 1.0f);
            float d = cm - gmean;
            between = fmaf(cnt, d * d, between);
        }
        between /= Sf;
        stats6[tid * 6 + 0] = between / fmaxf(var, 1e-6f);
        stats6[tid * 6 + 1] = tnan / Sf;
        stats6[tid * 6 + 2] = tuniq / Sf;
        stats6[tid * 6 + 3] = var;
        stats6[tid * 6 + 4] = tsumabs / Sf;
        stats6[tid * 6 + 5] = tmaxabs;
    }
    __syncthreads();

    // ---- MLP layer 1: h = gelu_exact(stats6 @ w1 + b1), 4 cols x 64 ----
    if (tid < COLS_PER_CTA * HID) {
        int ch = tid >> 6, j = tid & 63;
        float a1 = b1[j];
        #pragma unroll
        for (int i = 0; i < 6; i++)
            a1 = fmaf(stats6[ch * 6 + i], w1[i * HID + j], a1);
        hsm[ch * HID + j] = 0.5f * a1 * (1.0f + erff(a1 * 0.70710678118654752f));
    }
    __syncthreads();

    // ---- MLP layer 2: out = h @ w2 + b2, 4 cols x 128 (one output/thread) ----
    if (tid < COLS_PER_CTA * ODIM) {
        int ch = tid >> 7, k = tid & 127;
        float a2 = b2[k];
        #pragma unroll
        for (int j = 0; j < HID; j++)
            a2 = fmaf(hsm[ch * HID + j], w2s[j * ODIM + k], a2);
        out[(((size_t)b * F_DIM) + f0 + ch) * ODIM + k] = a2;
    }
}

extern "C" void kernel_launch(void* const* d_in, const int* in_sizes, int n_in,
                              void* d_out, int out_size) {
    const float* X  = (const float*)d_in[0];
    const int*   y  = (const int*)d_in[1];
    const float* w1 = (const float*)d_in[2];
    const float* b1 = (const float*)d_in[3];
    const float* w2 = (const float*)d_in[4];
    const float* b2 = (const float*)d_in[5];
    float* out = (float*)d_out;

    cudaFuncSetAttribute(stats_mlp_kernel,
                         cudaFuncAttributeMaxDynamicSharedMemorySize, SMEM_BYTES);

    sort_kernel<<<B_DIM, 256>>>(y);
    dim3 grid(F_DIM / COLS_PER_CTA, B_DIM);
    stats_mlp_kernel<<<grid, NTHREADS, SMEM_BYTES>>>(X, w1, b1, w2, b2, out);
}

// round 11
// speedup vs baseline: 2.3400x; 1.1393x over previous
#include <cuda_runtime.h>
#include <cuda_bf16.h>
#include <math.h>

// Problem constants
#define B_DIM 16
#define S_DIM 4096
#define F_DIM 512
#define NCLS 10
#define HID 64
#define ODIM 128

#define COLS_PER_CTA 4
#define NTHREADS 1024
#define ROWS_PER_THREAD 16
#define TAB_SLOTS 8192          // per-column slots (<=4096 distinct -> LF 0.5)
#define EMPTY_SLOT 0xFFFFFFFFu  // canonicalized values never have this bit pattern

// Shared memory (dynamic), bytes:
// phase 1: [0, 131072)        4 hash tables of 8192 u32
//          [131072, 139264)   perm (4096 u16, class-sorted row ids)
//          [139264, 204800)   bits stash (16 x 1024 u32)
//          [204800, 204864)   class_start (11 ints, padded)
//          [204864, 205056)   bins (4 cols x 10 classes f32, padded)
//          [205056, 205072)   uniqc (4 ints)
// phase 2 overlay (inside tables region, after sweep):
//          [0, 4096)          red: 32 warps x 32 floats
//          [4096, 4352)       tot: 4 cols x 8 stats
//          [4352, 4448)       stats6: 4 cols x 6
//          [4608, 5632)       h: 4 cols x 64
//          [8192, 40960)      w2 staged (64x128 f32)
#define OFF_TABLES   0
#define OFF_PERM     131072
#define OFF_BITS     139264
#define OFF_CS       204800
#define OFF_BINS     204864
#define OFF_UNIQ     205056
#define SMEM_BYTES   205312
#define OFF_RED      0
#define OFF_TOT      4096
#define OFF_STATS    4352
#define OFF_H        4608
#define OFF_W2       8192

__device__ float g_class_counts[B_DIM * NCLS];
__device__ int g_cs[B_DIM * 12];                    // class_start prefix per batch
__device__ unsigned short g_perm[B_DIM * S_DIM];    // class-sorted row ids

// ---- per-batch stable counting sort of row indices by class ----
__global__ void sort_kernel(const int* __restrict__ y) {
    __shared__ int scnt[256 * 10];
    __shared__ int spos[256 * 10];
    __shared__ int cs[12];
    const int t = threadIdx.x;
    const int b = blockIdx.x;
    const int* yb = y + b * S_DIM;

    #pragma unroll
    for (int c = 0; c < NCLS; c++) scnt[t * 10 + c] = 0;
    __syncthreads();
    #pragma unroll
    for (int i = 0; i < 16; i++) scnt[t * 10 + yb[t * 16 + i]]++;
    __syncthreads();
    if (t < NCLS) {
        int run = 0;
        for (int tt = 0; tt < 256; tt++) {
            spos[tt * 10 + t] = run;
            run += scnt[tt * 10 + t];
        }
        g_class_counts[b * NCLS + t] = (float)run;
        scnt[t] = run;
    }
    __syncthreads();
    if (t == 0) {
        int acc = 0;
        #pragma unroll
        for (int c = 0; c < NCLS; c++) { cs[c] = acc; acc += scnt[c]; }
        cs[10] = acc;
        #pragma unroll
        for (int c = 0; c < 11; c++) g_cs[b * 12 + c] = cs[c];
    }
    __syncthreads();
    #pragma unroll
    for (int i = 0; i < 16; i++) {
        int c = yb[t * 16 + i];
        int idx = cs[c] + spos[t * 10 + c];
        spos[t * 10 + c] = spos[t * 10 + c] + 1;
        g_perm[b * S_DIM + idx] = (unsigned short)(t * 16 + i);
    }
}

// Double-hash slot sequence: odd step over power-of-2 table covers all slots.
__device__ __forceinline__ unsigned int hslot(unsigned int bits, int r) {
    unsigned int h1 = (bits * 2654435761u) >> 19;            // 13 bits
    unsigned int st = (((bits * 0x85ebca6bu) >> 20) | 1u);   // odd step
    return (h1 + (unsigned int)r * st) & (TAB_SLOTS - 1);
}

__global__ __launch_bounds__(NTHREADS, 1)
void stats_mlp_kernel(const float* __restrict__ X,
                      const float* __restrict__ w1,
                      const float* __restrict__ b1,
                      const float* __restrict__ w2,
                      const float* __restrict__ b2,
                      float* __restrict__ out) {
    extern __shared__ char smem[];
    unsigned int* tables = (unsigned int*)(smem + OFF_TABLES);
    unsigned short* perm = (unsigned short*)(smem + OFF_PERM);
    unsigned int* bsm = (unsigned int*)(smem + OFF_BITS);   // [16][1024]
    int* cs = (int*)(smem + OFF_CS);
    float* bins = (float*)(smem + OFF_BINS);                // [col][class]
    int* uniqc = (int*)(smem + OFF_UNIQ);                   // [4]

    const int tid  = threadIdx.x;
    const int lane = tid & 31;
    const int wid  = tid >> 5;
    const int g  = blockIdx.x;       // feature group 0..127
    const int b  = blockIdx.y;       // batch 0..15
    const int f0 = g * COLS_PER_CTA;

    // init hash tables (vectorized)
    {
        uint4* tv = (uint4*)tables;
        uint4 e = make_uint4(EMPTY_SLOT, EMPTY_SLOT, EMPTY_SLOT, EMPTY_SLOT);
        #pragma unroll
        for (int i = 0; i < (COLS_PER_CTA * TAB_SLOTS / 4) / NTHREADS; i++)
            tv[tid + i * NTHREADS] = e;
    }
    // stage perm (8192B) via uint2
    {
        const uint2* ps = (const uint2*)(g_perm + b * S_DIM);
        uint2* pd = (uint2*)perm;
        pd[tid] = ps[tid];
    }
    if (tid < 11) cs[tid] = g_cs[b * 12 + tid];
    if (tid < COLS_PER_CTA * NCLS) bins[tid] = 0.0f;
    if (tid < COLS_PER_CTA) uniqc[tid] = 0;
    __syncthreads();

    const int col  = tid & 3;        // 4 consecutive lanes read 16 contiguous bytes
    const int r0   = tid >> 2;       // 0..255
    const int base = r0 * ROWS_PER_THREAD;

    float sumsq = 0.f, sumabs = 0.f, maxabs = 0.f, nanc = 0.f;
    float acc = 0.f;                 // running class-segment sum

    int cur = 0;
    #pragma unroll
    for (int c = 0; c < NCLS - 1; c++) cur += (cs[c + 1] <= base) ? 1 : 0;
    int nxt = cs[cur + 1];

    unsigned int* tab = tables + col * TAB_SLOTS;
    const float* Xb = X + ((size_t)b * S_DIM) * F_DIM + f0 + col;
    float* mybin = bins + col * NCLS;

    // ---- Phase A: stream X, compute stats, stash canonical bits ----
    #pragma unroll 4
    for (int i = 0; i < ROWS_PER_THREAD; i++) {
        const int p = base + i;
        if (p == nxt) {              // class boundary (rare)
            atomicAdd(mybin + cur, acc);
            acc = 0.f;
            do { cur++; nxt = cs[cur + 1]; } while (nxt == p);
        }
        int row = (int)perm[p];
        float x = __ldg(&Xb[(size_t)row * F_DIM]);
        bool isn = isnan(x);
        float v = isn ? 0.0f : x;
        nanc += isn ? 1.0f : 0.0f;
        acc += v;
        sumsq = fmaf(v, v, sumsq);
        float a = fabsf(v);
        sumabs += a;
        maxabs = fmaxf(maxabs, a);
        bsm[i * NTHREADS + tid] = __float_as_uint(v == 0.0f ? 0.0f : v);
    }
    atomicAdd(mybin + cur, acc);     // final segment flush

    // ---- Phase B: atomic-free scatter-verify insertion rounds ----
    {
        unsigned int undone = 0xFFFFu;
        int r = 0;
        while (__syncthreads_or((int)undone)) {   // also the round barrier
            unsigned int pend = 0;
            unsigned int m = undone;
            while (m) {
                int i = __ffs(m) - 1; m &= m - 1;
                unsigned int bits = bsm[i * NTHREADS + tid];
                // one-round-back recheck closes the duplicate-divergence race
                if (r > 0 && tab[hslot(bits, r - 1)] == bits) {
                    undone &= ~(1u << i);
                    continue;
                }
                unsigned int slot = hslot(bits, r);
                unsigned int c0 = tab[slot];
                if (c0 == bits) {
                    undone &= ~(1u << i);
                } else if (c0 == EMPTY_SLOT) {
                    tab[slot] = bits;            // racy store; verified below
                    pend |= (1u << i);
                }
            }
            __syncthreads();                     // stores drained before verify
            m = pend;
            while (m) {
                int i = __ffs(m) - 1; m &= m - 1;
                unsigned int bits = bsm[i * NTHREADS + tid];
                if (tab[hslot(bits, r)] == bits) undone &= ~(1u << i);
            }
            r++;
        }
    }

    // ---- sweep tables: uniq[col] = occupied slot count (deterministic ints) ----
    {
        const uint4* tv = (const uint4*)tables;
        int cnt = 0;
        #pragma unroll
        for (int i = 0; i < 8; i++) {
            uint4 w = tv[tid * 8 + i];
            cnt += (w.x != EMPTY_SLOT) + (w.y != EMPTY_SLOT)
                 + (w.z != EMPTY_SLOT) + (w.w != EMPTY_SLOT);
        }
        #pragma unroll
        for (int off = 16; off > 0; off >>= 1)
            cnt += __shfl_xor_sync(0xFFFFFFFFu, cnt, off);
        if (lane == 0) atomicAdd(&uniqc[tid >> 8], cnt);  // 32 int atomics total
    }
    __syncthreads();                 // sweep done; tables region -> overlay

    float* red    = (float*)(smem + OFF_RED);    // [32 warps][32]
    float* tot    = (float*)(smem + OFF_TOT);    // [4][8]
    float* stats6 = (float*)(smem + OFF_STATS);
    float* hsm    = (float*)(smem + OFF_H);
    float* w2s    = (float*)(smem + OFF_W2);

    // ---- warp butterfly reduce 4 stats to per-col (stop at offset 4) ----
    {
        float st[4] = {sumsq, sumabs, maxabs, nanc};
        #pragma unroll
        for (int k = 0; k < 4; k++) {
            float v = st[k];
            #pragma unroll
            for (int off = 16; off >= 4; off >>= 1) {
                float o = __shfl_xor_sync(0xFFFFFFFFu, v, off);
                v = (k == 2) ? fmaxf(v, o) : v + o;
            }
            st[k] = v;
        }
        if (lane < 4) {
            #pragma unroll
            for (int k = 0; k < 4; k++) red[wid * 32 + lane * 8 + k] = st[k];
        }
    }
    __syncthreads();

    // ---- cross-warp totals: threads 0..31, c=tid>>3, k=tid&7 (k<4 used) ----
    if (tid < 32 && (tid & 7) < 4) {
        int c = tid >> 3, k = tid & 7;
        float v = red[0 * 32 + c * 8 + k];
        #pragma unroll
        for (int w = 1; w < 32; w++) {
            float o = red[w * 32 + c * 8 + k];
            v = (k == 2) ? fmaxf(v, o) : v + o;
        }
        tot[c * 8 + k] = v;
    }
    // stage w2 (disjoint overlay region)
    {
        const float4* w2v = (const float4*)w2;
        float4* w2d = (float4*)w2s;
        #pragma unroll
        for (int i = 0; i < (HID * ODIM / 4) / NTHREADS; i++)
            w2d[tid + i * NTHREADS] = w2v[tid + i * NTHREADS];
    }
    __syncthreads();

    // ---- per-column final stats (threads 0..3) ----
    if (tid < COLS_PER_CTA) {
        const float Sf = (float)S_DIM;
        float tsumsq  = tot[tid * 8 + 0];
        float tsumabs = tot[tid * 8 + 1];
        float tmaxabs = tot[tid * 8 + 2];
        float tnan    = tot[tid * 8 + 3];
        float tuniq   = (float)uniqc[tid];
        float tsum = 0.f;
        #pragma unroll
        for (int c = 0; c < NCLS; c++) tsum += bins[tid * NCLS + c];
        float gmean = tsum / Sf;
        float var = fmaxf(tsumsq / Sf - gmean * gmean, 0.0f);
        float between = 0.0f;
        #pragma unroll
        for (int c = 0; c < NCLS; c++) {
            float cnt = g_class_counts[b * NCLS + c];
            float cm = bins[tid * NCLS + c] / fmaxf(cnt, 1.0f);
            float d = cm - gmean;
            between = fmaf(cnt, d * d, between);
        }
        between /= Sf;
        stats6[tid * 6 + 0] = between / fmaxf(var, 1e-6f);
        stats6[tid * 6 + 1] = tnan / Sf;
        stats6[tid * 6 + 2] = tuniq / Sf;
        stats6[tid * 6 + 3] = var;
        stats6[tid * 6 + 4] = tsumabs / Sf;
        stats6[tid * 6 + 5] = tmaxabs;
    }
    __syncthreads();

    // ---- MLP layer 1: h = gelu_exact(stats6 @ w1 + b1), 4 cols x 64 ----
    if (tid < COLS_PER_CTA * HID) {
        int ch = tid >> 6, j = tid & 63;
        float a1 = b1[j];
        #pragma unroll
        for (int i = 0; i < 6; i++)
            a1 = fmaf(stats6[ch * 6 + i], w1[i * HID + j], a1);
        hsm[ch * HID + j] = 0.5f * a1 * (1.0f + erff(a1 * 0.70710678118654752f));
    }
    __syncthreads();

    // ---- MLP layer 2: out = h @ w2 + b2, 4 cols x 128 (one output/thread) ----
    if (tid < COLS_PER_CTA * ODIM) {
        int ch = tid >> 7, k = tid & 127;
        float a2 = b2[k];
        #pragma unroll
        for (int j = 0; j < HID; j++)
            a2 = fmaf(hsm[ch * HID + j], w2s[j * ODIM + k], a2);
        out[(((size_t)b * F_DIM) + f0 + ch) * ODIM + k] = a2;
    }
}

extern "C" void kernel_launch(void* const* d_in, const int* in_sizes, int n_in,
                              void* d_out, int out_size) {
    const float* X  = (const float*)d_in[0];
    const int*   y  = (const int*)d_in[1];
    const float* w1 = (const float*)d_in[2];
    const float* b1 = (const float*)d_in[3];
    const float* w2 = (const float*)d_in[4];
    const float* b2 = (const float*)d_in[5];
    float* out = (float*)d_out;

    cudaFuncSetAttribute(stats_mlp_kernel,
                         cudaFuncAttributeMaxDynamicSharedMemorySize, SMEM_BYTES);

    sort_kernel<<<B_DIM, 256>>>(y);
    dim3 grid(F_DIM / COLS_PER_CTA, B_DIM);
    stats_mlp_kernel<<<grid, NTHREADS, SMEM_BYTES>>>(X, w1, b1, w2, b2, out);
}